// round 12
// baseline (speedup 1.0000x reference)
#include <cuda_runtime.h>
#include <cstdint>

#define Bc 256
#define Tc 512
#define Cc 256
#define Lc 64
#define GSP 68            // padded gathered row (65 used)
#define CHUNK 32
#define NCHUNK (Tc / CHUNK)   // 16
#define NTHR 512
#define NPROD 14          // producer warps (wid 2..15)
#define NBLK (Bc / 2)     // 128 blocks, 2 batch rows each
#define LOG2E 1.4426950408889634f
#define LN2 0.6931471805599453f
#define ESENT (-100000)

__device__ float g_loss[Bc];
__device__ int   g_ctr;          // zero-init; reset by last block each launch

// warp-collective: softmax of one logits row + gather 65 label classes
// (linear probs) into SMEM. Full warp must call.
__device__ __forceinline__ void softmax_row(
    const float* __restrict__ rf, const int* __restrict__ s_tg,
    float* __restrict__ out, int lane)
{
    const float4* rp = (const float4*)rf;
    const float4 v0 = rp[lane];
    const float4 v1 = rp[lane + 32];

    float m = fmaxf(fmaxf(fmaxf(v0.x, v0.y), fmaxf(v0.z, v0.w)),
                    fmaxf(fmaxf(v1.x, v1.y), fmaxf(v1.z, v1.w)));
    #pragma unroll
    for (int o = 16; o; o >>= 1) m = fmaxf(m, __shfl_xor_sync(0xffffffffu, m, o));

    float s = exp2f((v0.x - m) * LOG2E) + exp2f((v0.y - m) * LOG2E)
            + exp2f((v0.z - m) * LOG2E) + exp2f((v0.w - m) * LOG2E)
            + exp2f((v1.x - m) * LOG2E) + exp2f((v1.y - m) * LOG2E)
            + exp2f((v1.z - m) * LOG2E) + exp2f((v1.w - m) * LOG2E);
    #pragma unroll
    for (int o = 16; o; o >>= 1) s += __shfl_xor_sync(0xffffffffu, s, o);

    const float l2s = __log2f(s);
    #pragma unroll
    for (int j = lane; j < 65; j += 32) {
        const int cls = j ? s_tg[j - 1] : 0;
        out[j] = exp2f((rf[cls] - m) * LOG2E - l2s);   // rf[cls] is L1-hot
    }
}

// one alpha step; DO_RENORM toggles the exact pow2 renormalization
#define ASTEP(QPTR, DO_RENORM) do {                                        \
    const float lpb = (QPTR)[0];                                           \
    const float lpA = (QPTR)[j1];                                          \
    const float lpB = (QPTR)[j3];                                          \
    float pm = __shfl_up_sync(0xffffffffu, a3, 1);                         \
    int   pe = __shfl_up_sync(0xffffffffu, E,  1);                         \
    if (lane == 0) { pm = 0.f; pe = ESENT; }                               \
    const int eu = max(E, pe);                                             \
    const int dl = max(E  - eu, -127);                                     \
    const int dp = max(pe - eu, -127);                                     \
    const float sl  = __int_as_float((dl + 127) << 23);                    \
    const float spf = __int_as_float((dp + 127) << 23);                    \
    const float p = pm * spf;                                              \
    a0 *= sl; a1 *= sl; a2 *= sl; a3 *= sl; a4 *= sl;                      \
    const float n0 = (a0 + p) * lpb;                                       \
    const float n1 = fmaf(sk1f, p,  a0 + a1) * lpA;                        \
    const float n2 = (a1 + a2) * lpb;                                      \
    const float n3 = fmaf(sk3f, a1, a2 + a3) * lpB;                        \
    a4 = (a3 + a4) * lpb;                                                  \
    if (DO_RENORM) {                                                       \
        const float m4 = (lane == 31) ? a4 : 0.f;                          \
        const float mx = fmaxf(fmaxf(n0, n1), fmaxf(fmaxf(n2, n3), m4));   \
        const int kk = (__float_as_int(mx) >> 23) - 127;                   \
        const float sc = __int_as_float((127 - kk) << 23);                 \
        a0 = n0 * sc; a1 = n1 * sc; a2 = n2 * sc; a3 = n3 * sc; a4 *= sc;  \
        E = eu + kk;                                                       \
    } else {                                                               \
        a0 = n0; a1 = n1; a2 = n2; a3 = n3;                                \
        E = eu;                                                            \
    }                                                                      \
} while (0)

// ---------------------------------------------------------------------------
// Fused kernel: one block per TWO batch rows (grid 128 -> 1 block/SM, one
// wave). Warp 0 consumes row 2i, warp 1 consumes row 2i+1 (different SMSPs).
// Warps 2..15 are softmax producers filling both rows' SMEM double buffers
// one chunk ahead. One __syncthreads per 32-step chunk. Last block folds
// the deterministic batch mean.
// ---------------------------------------------------------------------------
__global__ __launch_bounds__(NTHR) void ctc_fused_kernel(
    const float* __restrict__ logits,
    const int* __restrict__ targets,
    const int* __restrict__ in_len,
    const int* __restrict__ tgt_len,
    float* __restrict__ d_out)
{
    const int tid  = threadIdx.x;
    const int wid  = tid >> 5;
    const int lane = tid & 31;
    const int b0   = blockIdx.x * 2;

    __shared__ float stg[2][2][CHUNK * GSP];   // [row][parity] 34816 B
    __shared__ int   s_tg[2][Lc];
    __shared__ float fin_m[2][132];
    __shared__ int   fin_e[2][33];
    __shared__ int   s_last;

    const int tlen0 = in_len[b0];
    const int tlen1 = in_len[b0 + 1];
    const int tmax  = max(tlen0, tlen1);

    if (tid < 2 * Lc)
        s_tg[tid >> 6][tid & 63] = targets[(b0 + (tid >> 6)) * Lc + (tid & 63)];
    __syncthreads();

    // fill chunk 0 of both rows with all 16 warps
    #pragma unroll 2
    for (int vr = wid; vr < 2 * CHUNK; vr += 16) {
        const int ps = vr / CHUNK, r = vr % CHUNK;
        softmax_row(logits + ((size_t)(b0 + ps) * Tc + r) * Cc,
                    s_tg[ps], &stg[ps][0][r * GSP], lane);
    }
    __syncthreads();

    // consumer state (warps 0 and 1 only)
    float a0 = 0.f, a1 = 0.f, a2 = 0.f, a3 = 0.f, a4 = 0.f;
    int   E  = ESENT;
    float sk1f = 0.f, sk3f = 0.f;
    int   j1 = 1, j3 = 2, mytlen = 0;
    if (wid < 2) {
        const int* tg = s_tg[wid];
        j1 = 2 * lane + 1;
        j3 = 2 * lane + 2;
        if (lane > 0) sk1f = (tg[2 * lane] != tg[2 * lane - 1]) ? 1.f : 0.f;
        sk3f = (tg[2 * lane + 1] != tg[2 * lane]) ? 1.f : 0.f;
        if (lane == 0) { a0 = stg[wid][0][0]; a1 = stg[wid][0][1]; E = 0; }
        mytlen = wid ? tlen1 : tlen0;
    }

    int t = 1;
    #pragma unroll 1
    for (int c = 0; c < NCHUNK; ++c) {
        if (wid < 2) {
            // ---- consume chunk c of my row (renorm every 2nd step) ----
            const float* __restrict__ sp = stg[wid][c & 1];
            const int tcend = min((c + 1) * CHUNK, mytlen);
            const float* q = sp + (t - c * CHUNK) * GSP;
            #pragma unroll 1
            for (; t + 1 < tcend; t += 2, q += 2 * GSP) {
                ASTEP(q, false);
                ASTEP(q + GSP, true);
            }
            if (t < tcend) { ASTEP(q, true); ++t; }
        } else {
            // ---- produce chunk c+1 for both rows ----
            const int base = (c + 1) * CHUNK;
            #pragma unroll 2
            for (int vr = wid - 2; vr < 2 * CHUNK; vr += NPROD) {
                const int ps = vr / CHUNK, r = vr % CHUNK;
                const int pt = base + r;
                const int ptl = ps ? tlen1 : tlen0;
                if (pt < ptl)       // warp-uniform predicate
                    softmax_row(logits + ((size_t)(b0 + ps) * Tc + pt) * Cc,
                                s_tg[ps], &stg[ps][(c + 1) & 1][r * GSP], lane);
            }
        }
        __syncthreads();
        if ((c + 1) * CHUNK >= tmax) break;
    }

    // consumer warps finalize their rows
    if (wid < 2) {
        fin_m[wid][4 * lane + 0] = a0;
        fin_m[wid][4 * lane + 1] = a1;
        fin_m[wid][4 * lane + 2] = a2;
        fin_m[wid][4 * lane + 3] = a3;
        fin_e[wid][lane] = E;
        if (lane == 31) { fin_m[wid][128] = a4; fin_e[wid][32] = E; }
        __syncwarp();

        if (lane == 0) {
            const int b  = b0 + wid;
            const int tl = tgt_len[b];
            const int s1 = 2 * tl, s2 = 2 * tl - 1;
            const float m1 = fin_m[wid][s1];  const int e1 = fin_e[wid][s1 >> 2];
            const float m2 = fin_m[wid][s2];  const int e2 = fin_e[wid][s2 >> 2];
            const int eu = max(e1, e2);
            const float f1 = __int_as_float((max(e1 - eu, -127) + 127) << 23);
            const float f2 = __int_as_float((max(e2 - eu, -127) + 127) << 23);
            const float sum = m1 * f1 + m2 * f2;
            float loss = 0.f;
            if (sum > 0.f) {
                loss = -LN2 * (__log2f(sum) + (float)eu);
                if (!(loss < 1e20f)) loss = 0.f;   // zero_infinity / NaN guard
            }
            g_loss[b] = loss / (float)tl;
        }
    }

    // last finished block computes the batch mean (deterministic fixed-order
    // reduction by one warp) and resets the counter for the next replay
    if (tid == 0) {
        __threadfence();
        s_last = (atomicAdd(&g_ctr, 1) == NBLK - 1);
    }
    __syncthreads();
    if (s_last && wid == 0) {
        __threadfence();
        float v = 0.f;
        #pragma unroll
        for (int i = 0; i < Bc / 32; ++i) v += g_loss[lane + i * 32];
        #pragma unroll
        for (int o = 16; o; o >>= 1) v += __shfl_xor_sync(0xffffffffu, v, o);
        if (lane == 0) { d_out[0] = v / (float)Bc; g_ctr = 0; }
    }
}

extern "C" void kernel_launch(void* const* d_in, const int* in_sizes, int n_in,
                              void* d_out, int out_size)
{
    const float* logits  = (const float*)d_in[0];   // [B,T,C] f32
    const int*   targets = (const int*)d_in[1];     // [B,L] i32
    const int*   in_len  = (const int*)d_in[2];     // [B] i32
    const int*   tgt_len = (const int*)d_in[3];     // [B] i32
    (void)in_sizes; (void)n_in; (void)out_size;

    ctc_fused_kernel<<<NBLK, NTHR>>>(logits, targets, in_len, tgt_len,
                                     (float*)d_out);
}